// round 12
// baseline (speedup 1.0000x reference)
#include <cuda_runtime.h>
#include <cuda_fp16.h>
#include <cstdint>

// Problem constants
#define B_    32
#define CIN   128
#define H_    56
#define HW    3136          // 56*56
#define COUT  256
#define KTOT  1152          // CIN*9
#define R_    16
#define KERN_PER_B (COUT*KTOT)      // 294912

// Scratch (static device arrays; no runtime allocation)
__device__ float g_gap[B_ * CIN];
__device__ float g_routing[B_ * 4];
// Mixed conv kernels, k' = r*128+ci ordering, fp16: [b][m][k']
__device__ __half g_Ah[(size_t)B_ * COUT * KTOT + 64];
// 9 shifted zero-padded fp16 copies of x: [r][b][ci][n]
#define XS_ELEMS ((size_t)9 * B_ * CIN * HW)
__device__ __half g_Xh[XS_ELEMS + 8192];

// ---------------------------------------------------------------------------
// helpers
// ---------------------------------------------------------------------------
__device__ __forceinline__ uint32_t smem_u32(const void* p) {
    uint32_t a;
    asm("{ .reg .u64 t; cvta.to.shared.u64 t, %1; cvt.u32.u64 %0, t; }"
        : "=r"(a) : "l"(p));
    return a;
}
__device__ __forceinline__ void ldmx4(uint32_t* r, uint32_t addr) {
    asm volatile("ldmatrix.sync.aligned.m8n8.x4.shared.b16 {%0,%1,%2,%3}, [%4];"
                 : "=r"(r[0]), "=r"(r[1]), "=r"(r[2]), "=r"(r[3]) : "r"(addr));
}
__device__ __forceinline__ void ldmx4t(uint32_t* r, uint32_t addr) {
    asm volatile("ldmatrix.sync.aligned.m8n8.x4.trans.shared.b16 {%0,%1,%2,%3}, [%4];"
                 : "=r"(r[0]), "=r"(r[1]), "=r"(r[2]), "=r"(r[3]) : "r"(addr));
}
__device__ __forceinline__ void mma_f16(float* d, const uint32_t* a, const uint32_t* b) {
    asm volatile(
        "mma.sync.aligned.m16n8k16.row.col.f32.f16.f16.f32 "
        "{%0,%1,%2,%3},{%4,%5,%6,%7},{%8,%9},{%0,%1,%2,%3};"
        : "+f"(d[0]), "+f"(d[1]), "+f"(d[2]), "+f"(d[3])
        : "r"(a[0]), "r"(a[1]), "r"(a[2]), "r"(a[3]), "r"(b[0]), "r"(b[1]));
}
__device__ __forceinline__ void cp16(uint32_t dst, const void* src) {
    asm volatile("cp.async.cg.shared.global [%0], [%1], 16;" :: "r"(dst), "l"(src));
}
__device__ __forceinline__ void cp_commit() {
    asm volatile("cp.async.commit_group;" ::: "memory");
}
__device__ __forceinline__ uint32_t pack_h2(__half a, __half b) {
    __half2 t = __halves2half2(a, b);
    return *reinterpret_cast<uint32_t*>(&t);
}

// ---------------------------------------------------------------------------
// 1) Global average pool
// ---------------------------------------------------------------------------
__global__ void gap_kernel(const float* __restrict__ x) {
    const int idx = blockIdx.x;
    const float* p = x + (size_t)idx * HW;
    float s = 0.f;
    for (int i = threadIdx.x; i < HW; i += 256) s += p[i];
    #pragma unroll
    for (int o = 16; o > 0; o >>= 1) s += __shfl_xor_sync(0xffffffffu, s, o);
    __shared__ float sm[8];
    if ((threadIdx.x & 31) == 0) sm[threadIdx.x >> 5] = s;
    __syncthreads();
    if (threadIdx.x < 8) {
        s = sm[threadIdx.x];
        s += __shfl_xor_sync(0xffu, s, 4);
        s += __shfl_xor_sync(0xffu, s, 2);
        s += __shfl_xor_sync(0xffu, s, 1);
        if (threadIdx.x == 0) g_gap[idx] = s * (1.0f / 3136.0f);
    }
}

// ---------------------------------------------------------------------------
// 2) Router MLP + softmax(logits/30)
// ---------------------------------------------------------------------------
__global__ void routing_kernel(const float* __restrict__ w1, const float* __restrict__ b1,
                               const float* __restrict__ w2, const float* __restrict__ b2) {
    const int b = threadIdx.x;
    if (b >= B_) return;
    float h[R_];
    #pragma unroll
    for (int r = 0; r < R_; r++) {
        float s = b1[r];
        for (int c = 0; c < CIN; c++) s += g_gap[b * CIN + c] * w1[r * CIN + c];
        h[r] = fmaxf(s, 0.f);
    }
    float lg[4];
    float mx = -1e30f;
    #pragma unroll
    for (int e = 0; e < 4; e++) {
        float s = b2[e];
        #pragma unroll
        for (int r = 0; r < R_; r++) s += h[r] * w2[e * R_ + r];
        lg[e] = s * (1.0f / 30.0f);
        mx = fmaxf(mx, lg[e]);
    }
    float den = 0.f;
    #pragma unroll
    for (int e = 0; e < 4; e++) { lg[e] = __expf(lg[e] - mx); den += lg[e]; }
    const float inv = 1.0f / den;
    #pragma unroll
    for (int e = 0; e < 4; e++) g_routing[b * 4 + e] = lg[e] * inv;
}

// ---------------------------------------------------------------------------
// 3) Shift + pad x into 9 fp16 copies: g_Xh[r][b][ci][n]
// ---------------------------------------------------------------------------
__global__ void shift_kernel(const float* __restrict__ x) {
    __shared__ float plane[HW];
    const int bc = blockIdx.x;               // b*CIN + ci
    const float* src = x + (size_t)bc * HW;
    for (int i = threadIdx.x; i < HW; i += 256) plane[i] = src[i];
    __syncthreads();
    const int b = bc >> 7, ci = bc & 127;
    for (int p = threadIdx.x; p < HW / 2; p += 256) {
        const int n0 = 2 * p;
        const int oh = n0 / H_;
        const int ow = n0 - oh * H_;         // even; ow+1 <= 55 (same row)
        #pragma unroll
        for (int r = 0; r < 9; r++) {
            const int dh = r / 3 - 1, dw = r % 3 - 1;
            const int ih = oh + dh;
            float v0 = 0.f, v1 = 0.f;
            if ((unsigned)ih < (unsigned)H_) {
                const int iw0 = ow + dw;
                if ((unsigned)iw0 < (unsigned)H_) v0 = plane[ih * H_ + iw0];
                const int iw1 = iw0 + 1;
                if ((unsigned)iw1 < (unsigned)H_) v1 = plane[ih * H_ + iw1];
            }
            const size_t off = ((size_t)(r * B_ + b) * CIN + ci) * (HW / 2) + p;
            ((uint32_t*)g_Xh)[off] = pack_h2(__float2half_rn(v0), __float2half_rn(v1));
        }
    }
}

// ---------------------------------------------------------------------------
// 4) Mix expert kernels -> g_Ah[b][m][k'] with k' = r*128+ci, fp16
// ---------------------------------------------------------------------------
__global__ void mix_kernel(const float* __restrict__ convs) {
    const int m = blockIdx.x;
    const int b = blockIdx.y;
    const float r0 = g_routing[b * 4 + 0];
    const float r1 = g_routing[b * 4 + 1];
    const float r2 = g_routing[b * 4 + 2];
    const float r3 = g_routing[b * 4 + 3];
    for (int p = threadIdx.x; p < KTOT / 2; p += 128) {   // p -> k' pair (2*p, 2*p+1)
        const int r = p >> 6;
        const int ci = (p & 63) * 2;
        const int base = m * KTOT + ci * 9 + r;
        const float* c0 = convs + base;
        float v0 = r0 * c0[0] + r1 * c0[KERN_PER_B] + r2 * c0[2 * KERN_PER_B] + r3 * c0[3 * KERN_PER_B];
        const float* c1 = convs + base + 9;
        float v1 = r0 * c1[0] + r1 * c1[KERN_PER_B] + r2 * c1[2 * KERN_PER_B] + r3 * c1[3 * KERN_PER_B];
        const size_t off = (size_t)(b * COUT + m) * (KTOT / 2) + p;
        ((uint32_t*)g_Ah)[off] = pack_h2(__float2half_rn(v0), __float2half_rn(v1));
    }
}

// ---------------------------------------------------------------------------
// 5) Per-sample GEMM on mma.sync (single-pass fp16), 3-stage cp.async ring,
//    ONE __syncthreads per stage (wait -> sync -> prefetch -> compute).
//    CTA tile 128m x 128n, BK=32 (36 stages), 8 warps -> warp tile 64m x 32n.
//    smem/stage (16 KB): A[128 rows][64B; chunk slot c^((row>>1)&3)]
//                        B[32 krows][256B; chunk slot c^(kr&7)]
// ---------------------------------------------------------------------------
#define STG    16384
#define SM_A(buf)  ((buf) * STG)
#define SM_B(buf)  ((buf) * STG + 8192)
#define SM_TOTAL   (3 * STG)

__global__ void __launch_bounds__(256, 2)
conv_mma(float* __restrict__ out) {
    extern __shared__ __align__(128) char smem[];
    const uint32_t sb = smem_u32(smem);

    const int tid  = threadIdx.x;
    const int wid  = tid >> 5;
    const int lane = tid & 31;
    const int wm   = wid & 1;          // 2 warps along m
    const int wn   = wid >> 1;         // 4 warps along n

    const int b  = blockIdx.z;
    const int m0 = blockIdx.y * 128;
    const int n0 = blockIdx.x * 128;

    float acc[4][4][4];
    #pragma unroll
    for (int i = 0; i < 4; i++)
        #pragma unroll
        for (int j = 0; j < 4; j++)
            #pragma unroll
            for (int q = 0; q < 4; q++) acc[i][j][q] = 0.f;

    // ---- stage loader (A: 512 cp16, B: 512 cp16 across 256 threads) ----
    auto load_stage = [&](int s, int buf) {
        const int r   = s >> 2;
        const int ci0 = (s & 3) * 32;
        // A: row m 0..127, chunk c 0..3 (64B rows)
        #pragma unroll
        for (int q = 0; q < 2; q++) {
            const int id  = q * 256 + tid;
            const int row = id >> 2;
            const int c   = id & 3;
            const __half* src =
                g_Ah + (size_t)(b * COUT + m0 + row) * KTOT + s * 32 + c * 8;
            cp16(sb + SM_A(buf) + row * 64 + ((c ^ ((row >> 1) & 3)) * 16), src);
        }
        // B: krow 0..31, chunk c 0..15 (256B rows)
        #pragma unroll
        for (int q = 0; q < 2; q++) {
            const int id = q * 256 + tid;
            const int kr = id >> 4;
            const int c  = id & 15;
            const __half* src =
                g_Xh + (size_t)((r * B_ + b) * CIN + ci0 + kr) * HW + n0 + c * 8;
            cp16(sb + SM_B(buf) + kr * 256 + ((c ^ (kr & 7)) * 16), src);
        }
        cp_commit();
    };

    load_stage(0, 0);
    load_stage(1, 1);

    for (int s = 0; s < 36; s++) {
        const int buf = s % 3;
        // 1) wait until stage s's group is complete (this thread's copies)
        if (s < 35) asm volatile("cp.async.wait_group 1;" ::: "memory");
        else        asm volatile("cp.async.wait_group 0;" ::: "memory");
        // 2) barrier: makes ALL threads' stage-s copies visible, and licenses
        //    overwriting buffer (s+2)%3 == (s-1)%3 (consumed last iteration)
        __syncthreads();
        // 3) prefetch stage s+2
        if (s + 2 < 36) load_stage(s + 2, (s + 2) % 3);

        // 4) compute stage s
        #pragma unroll
        for (int ks = 0; ks < 2; ks++) {
            // ---- A fragments ----
            uint32_t ah[4][4];
            #pragma unroll
            for (int mi = 0; mi < 4; mi++) {
                const int row = wm * 64 + mi * 16 + (lane & 15);
                const int cl  = ks * 2 + (lane >> 4);
                ldmx4(ah[mi], sb + SM_A(buf) + row * 64 + ((cl ^ ((row >> 1) & 3)) * 16));
            }
            // ---- B fragments (ldmatrix.trans from k-major) ----
            uint32_t bh[4][2];
            #pragma unroll
            for (int ni = 0; ni < 2; ni++) {
                const int mat = lane >> 3, j = lane & 7;
                const int kr  = ks * 16 + (mat & 1) * 8 + j;
                const int nc  = wn * 4 + ni * 2 + (mat >> 1);
                uint32_t t[4];
                ldmx4t(t, sb + SM_B(buf) + kr * 256 + ((nc ^ (kr & 7)) * 16));
                bh[ni * 2 + 0][0] = t[0]; bh[ni * 2 + 0][1] = t[1];
                bh[ni * 2 + 1][0] = t[2]; bh[ni * 2 + 1][1] = t[3];
            }
            #pragma unroll
            for (int mi = 0; mi < 4; mi++)
                #pragma unroll
                for (int nj = 0; nj < 4; nj++)
                    mma_f16(acc[mi][nj], ah[mi], bh[nj]);
        }
    }

    // ---- epilogue ----
    #pragma unroll
    for (int mi = 0; mi < 4; mi++) {
        const int m = m0 + wm * 64 + mi * 16 + (lane >> 2);
        #pragma unroll
        for (int nj = 0; nj < 4; nj++) {
            const int nn = n0 + wn * 32 + nj * 8 + (lane & 3) * 2;
            if (nn < HW) {
                float* o = out + (size_t)(b * COUT + m) * HW + nn;
                *(float2*)o = make_float2(acc[mi][nj][0], acc[mi][nj][1]);
                *(float2*)(o + 8 * HW) = make_float2(acc[mi][nj][2], acc[mi][nj][3]);
            }
        }
    }
}

// ---------------------------------------------------------------------------
extern "C" void kernel_launch(void* const* d_in, const int* in_sizes, int n_in,
                              void* d_out, int out_size) {
    const float* x     = (const float*)d_in[0];
    const float* convs = (const float*)d_in[1];
    const float* w1    = (const float*)d_in[2];
    const float* b1    = (const float*)d_in[3];
    const float* w2    = (const float*)d_in[4];
    const float* b2    = (const float*)d_in[5];
    float* out = (float*)d_out;

    cudaFuncSetAttribute(conv_mma, cudaFuncAttributeMaxDynamicSharedMemorySize, SM_TOTAL);

    gap_kernel<<<B_ * CIN, 256>>>(x);
    routing_kernel<<<1, 32>>>(w1, b1, w2, b2);
    shift_kernel<<<B_ * CIN, 256>>>(x);
    mix_kernel<<<dim3(COUT, B_), 128>>>(convs);
    conv_mma<<<dim3((HW + 127) / 128, COUT / 128, B_), 256, SM_TOTAL>>>(out);
}

// round 13
// speedup vs baseline: 1.5027x; 1.5027x over previous
#include <cuda_runtime.h>
#include <cuda_fp16.h>
#include <cstdint>

// Problem constants
#define B_    32
#define CIN   128
#define H_    56
#define HW    3136          // 56*56
#define COUT  256
#define KTOT  1152          // CIN*9
#define R_    16
#define KERN_PER_B (COUT*KTOT)      // 294912

// Scratch (static device arrays; no runtime allocation)
__device__ float g_gap[B_ * CIN];
__device__ float g_routing[B_ * 4];
// Mixed conv kernels, k' = r*128+ci ordering, fp16: [b][m][k']
__device__ __half g_Ah[(size_t)B_ * COUT * KTOT + 64];
// 9 shifted zero-padded fp16 copies of x: [r][b][ci][n]
#define XS_ELEMS ((size_t)9 * B_ * CIN * HW)
__device__ __half g_Xh[XS_ELEMS + 8192];

// ---------------------------------------------------------------------------
// helpers
// ---------------------------------------------------------------------------
__device__ __forceinline__ uint32_t smem_u32(const void* p) {
    uint32_t a;
    asm("{ .reg .u64 t; cvta.to.shared.u64 t, %1; cvt.u32.u64 %0, t; }"
        : "=r"(a) : "l"(p));
    return a;
}
__device__ __forceinline__ void ldmx4(uint32_t* r, uint32_t addr) {
    asm volatile("ldmatrix.sync.aligned.m8n8.x4.shared.b16 {%0,%1,%2,%3}, [%4];"
                 : "=r"(r[0]), "=r"(r[1]), "=r"(r[2]), "=r"(r[3]) : "r"(addr));
}
__device__ __forceinline__ void ldmx4t(uint32_t* r, uint32_t addr) {
    asm volatile("ldmatrix.sync.aligned.m8n8.x4.trans.shared.b16 {%0,%1,%2,%3}, [%4];"
                 : "=r"(r[0]), "=r"(r[1]), "=r"(r[2]), "=r"(r[3]) : "r"(addr));
}
__device__ __forceinline__ void mma_f16(float* d, const uint32_t* a, const uint32_t* b) {
    asm volatile(
        "mma.sync.aligned.m16n8k16.row.col.f32.f16.f16.f32 "
        "{%0,%1,%2,%3},{%4,%5,%6,%7},{%8,%9},{%0,%1,%2,%3};"
        : "+f"(d[0]), "+f"(d[1]), "+f"(d[2]), "+f"(d[3])
        : "r"(a[0]), "r"(a[1]), "r"(a[2]), "r"(a[3]), "r"(b[0]), "r"(b[1]));
}
__device__ __forceinline__ void cp16(uint32_t dst, const void* src) {
    asm volatile("cp.async.cg.shared.global [%0], [%1], 16;" :: "r"(dst), "l"(src));
}
__device__ __forceinline__ void cp_commit() {
    asm volatile("cp.async.commit_group;" ::: "memory");
}
__device__ __forceinline__ uint32_t pack_h2(__half a, __half b) {
    __half2 t = __halves2half2(a, b);
    return *reinterpret_cast<uint32_t*>(&t);
}

// ---------------------------------------------------------------------------
// 1) Global average pool
// ---------------------------------------------------------------------------
__global__ void gap_kernel(const float* __restrict__ x) {
    const int idx = blockIdx.x;
    const float* p = x + (size_t)idx * HW;
    float s = 0.f;
    for (int i = threadIdx.x; i < HW; i += 256) s += p[i];
    #pragma unroll
    for (int o = 16; o > 0; o >>= 1) s += __shfl_xor_sync(0xffffffffu, s, o);
    __shared__ float sm[8];
    if ((threadIdx.x & 31) == 0) sm[threadIdx.x >> 5] = s;
    __syncthreads();
    if (threadIdx.x < 8) {
        s = sm[threadIdx.x];
        s += __shfl_xor_sync(0xffu, s, 4);
        s += __shfl_xor_sync(0xffu, s, 2);
        s += __shfl_xor_sync(0xffu, s, 1);
        if (threadIdx.x == 0) g_gap[idx] = s * (1.0f / 3136.0f);
    }
}

// ---------------------------------------------------------------------------
// 2) Router MLP + softmax(logits/30)
// ---------------------------------------------------------------------------
__global__ void routing_kernel(const float* __restrict__ w1, const float* __restrict__ b1,
                               const float* __restrict__ w2, const float* __restrict__ b2) {
    const int b = threadIdx.x;
    if (b >= B_) return;
    float h[R_];
    #pragma unroll
    for (int r = 0; r < R_; r++) {
        float s = b1[r];
        for (int c = 0; c < CIN; c++) s += g_gap[b * CIN + c] * w1[r * CIN + c];
        h[r] = fmaxf(s, 0.f);
    }
    float lg[4];
    float mx = -1e30f;
    #pragma unroll
    for (int e = 0; e < 4; e++) {
        float s = b2[e];
        #pragma unroll
        for (int r = 0; r < R_; r++) s += h[r] * w2[e * R_ + r];
        lg[e] = s * (1.0f / 30.0f);
        mx = fmaxf(mx, lg[e]);
    }
    float den = 0.f;
    #pragma unroll
    for (int e = 0; e < 4; e++) { lg[e] = __expf(lg[e] - mx); den += lg[e]; }
    const float inv = 1.0f / den;
    #pragma unroll
    for (int e = 0; e < 4; e++) g_routing[b * 4 + e] = lg[e] * inv;
}

// ---------------------------------------------------------------------------
// 3) Shift + pad x into 9 fp16 copies: g_Xh[r][b][ci][n]
// ---------------------------------------------------------------------------
__global__ void shift_kernel(const float* __restrict__ x) {
    __shared__ float plane[HW];
    const int bc = blockIdx.x;               // b*CIN + ci
    const float* src = x + (size_t)bc * HW;
    for (int i = threadIdx.x; i < HW; i += 256) plane[i] = src[i];
    __syncthreads();
    const int b = bc >> 7, ci = bc & 127;
    for (int p = threadIdx.x; p < HW / 2; p += 256) {
        const int n0 = 2 * p;
        const int oh = n0 / H_;
        const int ow = n0 - oh * H_;         // even; ow+1 <= 55 (same row)
        #pragma unroll
        for (int r = 0; r < 9; r++) {
            const int dh = r / 3 - 1, dw = r % 3 - 1;
            const int ih = oh + dh;
            float v0 = 0.f, v1 = 0.f;
            if ((unsigned)ih < (unsigned)H_) {
                const int iw0 = ow + dw;
                if ((unsigned)iw0 < (unsigned)H_) v0 = plane[ih * H_ + iw0];
                const int iw1 = iw0 + 1;
                if ((unsigned)iw1 < (unsigned)H_) v1 = plane[ih * H_ + iw1];
            }
            const size_t off = ((size_t)(r * B_ + b) * CIN + ci) * (HW / 2) + p;
            ((uint32_t*)g_Xh)[off] = pack_h2(__float2half_rn(v0), __float2half_rn(v1));
        }
    }
}

// ---------------------------------------------------------------------------
// 4) Mix expert kernels -> g_Ah[b][m][k'] with k' = r*128+ci, fp16
// ---------------------------------------------------------------------------
__global__ void mix_kernel(const float* __restrict__ convs) {
    const int m = blockIdx.x;
    const int b = blockIdx.y;
    const float r0 = g_routing[b * 4 + 0];
    const float r1 = g_routing[b * 4 + 1];
    const float r2 = g_routing[b * 4 + 2];
    const float r3 = g_routing[b * 4 + 3];
    for (int p = threadIdx.x; p < KTOT / 2; p += 128) {   // p -> k' pair (2*p, 2*p+1)
        const int r = p >> 6;
        const int ci = (p & 63) * 2;
        const int base = m * KTOT + ci * 9 + r;
        const float* c0 = convs + base;
        float v0 = r0 * c0[0] + r1 * c0[KERN_PER_B] + r2 * c0[2 * KERN_PER_B] + r3 * c0[3 * KERN_PER_B];
        const float* c1 = convs + base + 9;
        float v1 = r0 * c1[0] + r1 * c1[KERN_PER_B] + r2 * c1[2 * KERN_PER_B] + r3 * c1[3 * KERN_PER_B];
        const size_t off = (size_t)(b * COUT + m) * (KTOT / 2) + p;
        ((uint32_t*)g_Ah)[off] = pack_h2(__float2half_rn(v0), __float2half_rn(v1));
    }
}

// ---------------------------------------------------------------------------
// 5) Per-sample GEMM on mma.sync (single-pass fp16), 4-stage cp.async ring,
//    ONE __syncthreads per stage (wait -> sync -> prefetch -> compute).
//    CTA tile 128m x 128n, BK=32 (36 stages), 8 warps -> warp tile 64m x 32n.
//    smem/stage (16 KB): A[128 rows][64B; chunk slot c^((row>>1)&3)]
//                        B[32 krows][256B; chunk slot c^(kr&7)]
// ---------------------------------------------------------------------------
#define STG    16384
#define NSTG   4
#define SM_A(buf)  ((buf) * STG)
#define SM_B(buf)  ((buf) * STG + 8192)
#define SM_TOTAL   (NSTG * STG)

__global__ void __launch_bounds__(256, 2)
conv_mma(float* __restrict__ out) {
    extern __shared__ __align__(128) char smem[];
    const uint32_t sb = smem_u32(smem);

    const int tid  = threadIdx.x;
    const int wid  = tid >> 5;
    const int lane = tid & 31;
    const int wm   = wid & 1;          // 2 warps along m
    const int wn   = wid >> 1;         // 4 warps along n

    const int b  = blockIdx.z;
    const int m0 = blockIdx.y * 128;
    const int n0 = blockIdx.x * 128;

    float acc[4][4][4];
    #pragma unroll
    for (int i = 0; i < 4; i++)
        #pragma unroll
        for (int j = 0; j < 4; j++)
            #pragma unroll
            for (int q = 0; q < 4; q++) acc[i][j][q] = 0.f;

    // ---- stage loader (A: 512 cp16, B: 512 cp16 across 256 threads) ----
    auto load_stage = [&](int s, int buf) {
        const int r   = s >> 2;
        const int ci0 = (s & 3) * 32;
        // A: row m 0..127, chunk c 0..3 (64B rows)
        #pragma unroll
        for (int q = 0; q < 2; q++) {
            const int id  = q * 256 + tid;
            const int row = id >> 2;
            const int c   = id & 3;
            const __half* src =
                g_Ah + (size_t)(b * COUT + m0 + row) * KTOT + s * 32 + c * 8;
            cp16(sb + SM_A(buf) + row * 64 + ((c ^ ((row >> 1) & 3)) * 16), src);
        }
        // B: krow 0..31, chunk c 0..15 (256B rows)
        #pragma unroll
        for (int q = 0; q < 2; q++) {
            const int id = q * 256 + tid;
            const int kr = id >> 4;
            const int c  = id & 15;
            const __half* src =
                g_Xh + (size_t)((r * B_ + b) * CIN + ci0 + kr) * HW + n0 + c * 8;
            cp16(sb + SM_B(buf) + kr * 256 + ((c ^ (kr & 7)) * 16), src);
        }
        cp_commit();
    };

    load_stage(0, 0);
    load_stage(1, 1);
    load_stage(2, 2);

    for (int s = 0; s < 36; s++) {
        const int buf = s & 3;                 // NSTG = 4
        // 1) wait until stage s's group is complete (this thread's copies).
        //    Outstanding here: s, s+1, s+2 (s+3 not yet issued).
        if (s < 34)      asm volatile("cp.async.wait_group 2;" ::: "memory");
        else if (s < 35) asm volatile("cp.async.wait_group 1;" ::: "memory");
        else             asm volatile("cp.async.wait_group 0;" ::: "memory");
        // 2) barrier: all threads' stage-s copies visible; licenses overwrite
        //    of buffer (s+3)%4 == (s-1)%4 (consumed last iteration)
        __syncthreads();
        // 3) prefetch stage s+3
        if (s + 3 < 36) load_stage(s + 3, (s + 3) & 3);

        // 4) compute stage s
        #pragma unroll
        for (int ks = 0; ks < 2; ks++) {
            // ---- A fragments ----
            uint32_t ah[4][4];
            #pragma unroll
            for (int mi = 0; mi < 4; mi++) {
                const int row = wm * 64 + mi * 16 + (lane & 15);
                const int cl  = ks * 2 + (lane >> 4);
                ldmx4(ah[mi], sb + SM_A(buf) + row * 64 + ((cl ^ ((row >> 1) & 3)) * 16));
            }
            // ---- B fragments (ldmatrix.trans from k-major) ----
            uint32_t bh[4][2];
            #pragma unroll
            for (int ni = 0; ni < 2; ni++) {
                const int mat = lane >> 3, j = lane & 7;
                const int kr  = ks * 16 + (mat & 1) * 8 + j;
                const int nc  = wn * 4 + ni * 2 + (mat >> 1);
                uint32_t t[4];
                ldmx4t(t, sb + SM_B(buf) + kr * 256 + ((nc ^ (kr & 7)) * 16));
                bh[ni * 2 + 0][0] = t[0]; bh[ni * 2 + 0][1] = t[1];
                bh[ni * 2 + 1][0] = t[2]; bh[ni * 2 + 1][1] = t[3];
            }
            #pragma unroll
            for (int mi = 0; mi < 4; mi++)
                #pragma unroll
                for (int nj = 0; nj < 4; nj++)
                    mma_f16(acc[mi][nj], ah[mi], bh[nj]);
        }
    }

    // ---- epilogue ----
    #pragma unroll
    for (int mi = 0; mi < 4; mi++) {
        const int m = m0 + wm * 64 + mi * 16 + (lane >> 2);
        #pragma unroll
        for (int nj = 0; nj < 4; nj++) {
            const int nn = n0 + wn * 32 + nj * 8 + (lane & 3) * 2;
            if (nn < HW) {
                float* o = out + (size_t)(b * COUT + m) * HW + nn;
                *(float2*)o = make_float2(acc[mi][nj][0], acc[mi][nj][1]);
                *(float2*)(o + 8 * HW) = make_float2(acc[mi][nj][2], acc[mi][nj][3]);
            }
        }
    }
}

// ---------------------------------------------------------------------------
extern "C" void kernel_launch(void* const* d_in, const int* in_sizes, int n_in,
                              void* d_out, int out_size) {
    const float* x     = (const float*)d_in[0];
    const float* convs = (const float*)d_in[1];
    const float* w1    = (const float*)d_in[2];
    const float* b1    = (const float*)d_in[3];
    const float* w2    = (const float*)d_in[4];
    const float* b2    = (const float*)d_in[5];
    float* out = (float*)d_out;

    cudaFuncSetAttribute(conv_mma, cudaFuncAttributeMaxDynamicSharedMemorySize, SM_TOTAL);

    gap_kernel<<<B_ * CIN, 256>>>(x);
    routing_kernel<<<1, 32>>>(w1, b1, w2, b2);
    shift_kernel<<<B_ * CIN, 256>>>(x);
    mix_kernel<<<dim3(COUT, B_), 128>>>(convs);
    conv_mma<<<dim3((HW + 127) / 128, COUT / 128, B_), 256, SM_TOTAL>>>(out);
}

// round 14
// speedup vs baseline: 1.5166x; 1.0093x over previous
#include <cuda_runtime.h>
#include <cuda_fp16.h>
#include <cstdint>

// Problem constants
#define B_    32
#define CIN   128
#define H_    56
#define HW    3136          // 56*56
#define COUT  256
#define KTOT  1152          // CIN*9
#define R_    16
#define KERN_PER_B (COUT*KTOT)      // 294912

// Scratch (static device arrays; no runtime allocation)
__device__ float g_gap[B_ * CIN];
__device__ float g_routing[B_ * 4];
// Mixed conv kernels, k' = r*128+ci ordering, fp16: [b][m][k']
__device__ __half g_Ah[(size_t)B_ * COUT * KTOT + 64];
// 9 shifted zero-padded fp16 copies of x: [r][b][ci][n]
#define XS_ELEMS ((size_t)9 * B_ * CIN * HW)
__device__ __half g_Xh[XS_ELEMS + 8192];

// ---------------------------------------------------------------------------
// helpers
// ---------------------------------------------------------------------------
__device__ __forceinline__ uint32_t smem_u32(const void* p) {
    uint32_t a;
    asm("{ .reg .u64 t; cvta.to.shared.u64 t, %1; cvt.u32.u64 %0, t; }"
        : "=r"(a) : "l"(p));
    return a;
}
__device__ __forceinline__ void ldmx4(uint32_t* r, uint32_t addr) {
    asm volatile("ldmatrix.sync.aligned.m8n8.x4.shared.b16 {%0,%1,%2,%3}, [%4];"
                 : "=r"(r[0]), "=r"(r[1]), "=r"(r[2]), "=r"(r[3]) : "r"(addr));
}
__device__ __forceinline__ void ldmx4t(uint32_t* r, uint32_t addr) {
    asm volatile("ldmatrix.sync.aligned.m8n8.x4.trans.shared.b16 {%0,%1,%2,%3}, [%4];"
                 : "=r"(r[0]), "=r"(r[1]), "=r"(r[2]), "=r"(r[3]) : "r"(addr));
}
__device__ __forceinline__ void mma_f16(float* d, const uint32_t* a, const uint32_t* b) {
    asm volatile(
        "mma.sync.aligned.m16n8k16.row.col.f32.f16.f16.f32 "
        "{%0,%1,%2,%3},{%4,%5,%6,%7},{%8,%9},{%0,%1,%2,%3};"
        : "+f"(d[0]), "+f"(d[1]), "+f"(d[2]), "+f"(d[3])
        : "r"(a[0]), "r"(a[1]), "r"(a[2]), "r"(a[3]), "r"(b[0]), "r"(b[1]));
}
__device__ __forceinline__ void cp16(uint32_t dst, const void* src) {
    asm volatile("cp.async.cg.shared.global [%0], [%1], 16;" :: "r"(dst), "l"(src));
}
__device__ __forceinline__ void cp_commit() {
    asm volatile("cp.async.commit_group;" ::: "memory");
}
__device__ __forceinline__ uint32_t pack_h2(__half a, __half b) {
    __half2 t = __halves2half2(a, b);
    return *reinterpret_cast<uint32_t*>(&t);
}

// ---------------------------------------------------------------------------
// 1) Global average pool
// ---------------------------------------------------------------------------
__global__ void gap_kernel(const float* __restrict__ x) {
    const int idx = blockIdx.x;
    const float* p = x + (size_t)idx * HW;
    float s = 0.f;
    for (int i = threadIdx.x; i < HW; i += 256) s += p[i];
    #pragma unroll
    for (int o = 16; o > 0; o >>= 1) s += __shfl_xor_sync(0xffffffffu, s, o);
    __shared__ float sm[8];
    if ((threadIdx.x & 31) == 0) sm[threadIdx.x >> 5] = s;
    __syncthreads();
    if (threadIdx.x < 8) {
        s = sm[threadIdx.x];
        s += __shfl_xor_sync(0xffu, s, 4);
        s += __shfl_xor_sync(0xffu, s, 2);
        s += __shfl_xor_sync(0xffu, s, 1);
        if (threadIdx.x == 0) g_gap[idx] = s * (1.0f / 3136.0f);
    }
}

// ---------------------------------------------------------------------------
// 2) Router MLP + softmax(logits/30)
// ---------------------------------------------------------------------------
__global__ void routing_kernel(const float* __restrict__ w1, const float* __restrict__ b1,
                               const float* __restrict__ w2, const float* __restrict__ b2) {
    const int b = threadIdx.x;
    if (b >= B_) return;
    float h[R_];
    #pragma unroll
    for (int r = 0; r < R_; r++) {
        float s = b1[r];
        for (int c = 0; c < CIN; c++) s += g_gap[b * CIN + c] * w1[r * CIN + c];
        h[r] = fmaxf(s, 0.f);
    }
    float lg[4];
    float mx = -1e30f;
    #pragma unroll
    for (int e = 0; e < 4; e++) {
        float s = b2[e];
        #pragma unroll
        for (int r = 0; r < R_; r++) s += h[r] * w2[e * R_ + r];
        lg[e] = s * (1.0f / 30.0f);
        mx = fmaxf(mx, lg[e]);
    }
    float den = 0.f;
    #pragma unroll
    for (int e = 0; e < 4; e++) { lg[e] = __expf(lg[e] - mx); den += lg[e]; }
    const float inv = 1.0f / den;
    #pragma unroll
    for (int e = 0; e < 4; e++) g_routing[b * 4 + e] = lg[e] * inv;
}

// ---------------------------------------------------------------------------
// 3) Shift + pad x into 9 fp16 copies: g_Xh[r][b][ci][n]
// ---------------------------------------------------------------------------
__global__ void shift_kernel(const float* __restrict__ x) {
    __shared__ float plane[HW];
    const int bc = blockIdx.x;               // b*CIN + ci
    const float* src = x + (size_t)bc * HW;
    for (int i = threadIdx.x; i < HW; i += 256) plane[i] = src[i];
    __syncthreads();
    const int b = bc >> 7, ci = bc & 127;
    for (int p = threadIdx.x; p < HW / 2; p += 256) {
        const int n0 = 2 * p;
        const int oh = n0 / H_;
        const int ow = n0 - oh * H_;         // even; ow+1 <= 55 (same row)
        #pragma unroll
        for (int r = 0; r < 9; r++) {
            const int dh = r / 3 - 1, dw = r % 3 - 1;
            const int ih = oh + dh;
            float v0 = 0.f, v1 = 0.f;
            if ((unsigned)ih < (unsigned)H_) {
                const int iw0 = ow + dw;
                if ((unsigned)iw0 < (unsigned)H_) v0 = plane[ih * H_ + iw0];
                const int iw1 = iw0 + 1;
                if ((unsigned)iw1 < (unsigned)H_) v1 = plane[ih * H_ + iw1];
            }
            const size_t off = ((size_t)(r * B_ + b) * CIN + ci) * (HW / 2) + p;
            ((uint32_t*)g_Xh)[off] = pack_h2(__float2half_rn(v0), __float2half_rn(v1));
        }
    }
}

// ---------------------------------------------------------------------------
// 4) Mix expert kernels -> g_Ah[b][m][k'] with k' = r*128+ci, fp16
// ---------------------------------------------------------------------------
__global__ void mix_kernel(const float* __restrict__ convs) {
    const int m = blockIdx.x;
    const int b = blockIdx.y;
    const float r0 = g_routing[b * 4 + 0];
    const float r1 = g_routing[b * 4 + 1];
    const float r2 = g_routing[b * 4 + 2];
    const float r3 = g_routing[b * 4 + 3];
    for (int p = threadIdx.x; p < KTOT / 2; p += 128) {   // p -> k' pair (2*p, 2*p+1)
        const int r = p >> 6;
        const int ci = (p & 63) * 2;
        const int base = m * KTOT + ci * 9 + r;
        const float* c0 = convs + base;
        float v0 = r0 * c0[0] + r1 * c0[KERN_PER_B] + r2 * c0[2 * KERN_PER_B] + r3 * c0[3 * KERN_PER_B];
        const float* c1 = convs + base + 9;
        float v1 = r0 * c1[0] + r1 * c1[KERN_PER_B] + r2 * c1[2 * KERN_PER_B] + r3 * c1[3 * KERN_PER_B];
        const size_t off = (size_t)(b * COUT + m) * (KTOT / 2) + p;
        ((uint32_t*)g_Ah)[off] = pack_h2(__float2half_rn(v0), __float2half_rn(v1));
    }
}

// ---------------------------------------------------------------------------
// 5) Per-sample GEMM on mma.sync (single-pass fp16), BK=64 (18 stages),
//    3-stage cp.async ring, ONE __syncthreads per stage
//    (wait -> sync -> prefetch -> compute; 4-deep unrolled ks window).
//    CTA tile 128m x 128n, 8 warps -> warp tile 64m x 32n.
//    smem/stage (32 KB): A[128 rows][128B; chunk slot c^(row&7)]
//                        B[64 krows][256B; chunk slot c^(kr&7)]
// ---------------------------------------------------------------------------
#define STG    32768
#define NSTG   3
#define SM_A(buf)  ((buf) * STG)
#define SM_B(buf)  ((buf) * STG + 16384)
#define SM_TOTAL   (NSTG * STG)

__global__ void __launch_bounds__(256, 2)
conv_mma(float* __restrict__ out) {
    extern __shared__ __align__(128) char smem[];
    const uint32_t sb = smem_u32(smem);

    const int tid  = threadIdx.x;
    const int wid  = tid >> 5;
    const int lane = tid & 31;
    const int wm   = wid & 1;          // 2 warps along m
    const int wn   = wid >> 1;         // 4 warps along n

    const int b  = blockIdx.z;
    const int m0 = blockIdx.y * 128;
    const int n0 = blockIdx.x * 128;

    float acc[4][4][4];
    #pragma unroll
    for (int i = 0; i < 4; i++)
        #pragma unroll
        for (int j = 0; j < 4; j++)
            #pragma unroll
            for (int q = 0; q < 4; q++) acc[i][j][q] = 0.f;

    // ---- stage loader (A: 1024 cp16, B: 1024 cp16 across 256 threads) ----
    auto load_stage = [&](int s, int buf) {
        const int r   = s >> 1;
        const int ci0 = (s & 1) * 64;
        // A: row m 0..127, chunk c 0..7 (128B rows)
        #pragma unroll
        for (int q = 0; q < 4; q++) {
            const int id  = q * 256 + tid;
            const int row = id >> 3;
            const int c   = id & 7;
            const __half* src =
                g_Ah + (size_t)(b * COUT + m0 + row) * KTOT + s * 64 + c * 8;
            cp16(sb + SM_A(buf) + row * 128 + ((c ^ (row & 7)) * 16), src);
        }
        // B: krow 0..63, chunk c 0..15 (256B rows)
        #pragma unroll
        for (int q = 0; q < 4; q++) {
            const int id = q * 256 + tid;
            const int kr = id >> 4;
            const int c  = id & 15;
            const __half* src =
                g_Xh + (size_t)((r * B_ + b) * CIN + ci0 + kr) * HW + n0 + c * 8;
            cp16(sb + SM_B(buf) + kr * 256 + ((c ^ (kr & 7)) * 16), src);
        }
        cp_commit();
    };

    load_stage(0, 0);
    load_stage(1, 1);

    for (int s = 0; s < 18; s++) {
        const int buf = s % 3;
        // 1) wait until stage s's group is complete (this thread's copies)
        if (s < 17) asm volatile("cp.async.wait_group 1;" ::: "memory");
        else        asm volatile("cp.async.wait_group 0;" ::: "memory");
        // 2) barrier: all threads' stage-s copies visible; licenses overwrite
        //    of buffer (s+2)%3 == (s-1)%3 (consumed last iteration)
        __syncthreads();
        // 3) prefetch stage s+2
        if (s + 2 < 18) load_stage(s + 2, (s + 2) % 3);

        // 4) compute stage s — 4-deep unrolled ks window for ILP
        #pragma unroll
        for (int ks = 0; ks < 4; ks++) {
            // ---- A fragments ----
            uint32_t ah[4][4];
            #pragma unroll
            for (int mi = 0; mi < 4; mi++) {
                const int row = wm * 64 + mi * 16 + (lane & 15);
                const int cl  = ks * 2 + (lane >> 4);
                ldmx4(ah[mi], sb + SM_A(buf) + row * 128 + ((cl ^ (row & 7)) * 16));
            }
            // ---- B fragments (ldmatrix.trans from k-major) ----
            uint32_t bh[4][2];
            #pragma unroll
            for (int ni = 0; ni < 2; ni++) {
                const int mat = lane >> 3, j = lane & 7;
                const int kr  = ks * 16 + (mat & 1) * 8 + j;
                const int nc  = wn * 4 + ni * 2 + (mat >> 1);
                uint32_t t[4];
                ldmx4t(t, sb + SM_B(buf) + kr * 256 + ((nc ^ (kr & 7)) * 16));
                bh[ni * 2 + 0][0] = t[0]; bh[ni * 2 + 0][1] = t[1];
                bh[ni * 2 + 1][0] = t[2]; bh[ni * 2 + 1][1] = t[3];
            }
            #pragma unroll
            for (int mi = 0; mi < 4; mi++)
                #pragma unroll
                for (int nj = 0; nj < 4; nj++)
                    mma_f16(acc[mi][nj], ah[mi], bh[nj]);
        }
    }

    // ---- epilogue ----
    #pragma unroll
    for (int mi = 0; mi < 4; mi++) {
        const int m = m0 + wm * 64 + mi * 16 + (lane >> 2);
        #pragma unroll
        for (int nj = 0; nj < 4; nj++) {
            const int nn = n0 + wn * 32 + nj * 8 + (lane & 3) * 2;
            if (nn < HW) {
                float* o = out + (size_t)(b * COUT + m) * HW + nn;
                *(float2*)o = make_float2(acc[mi][nj][0], acc[mi][nj][1]);
                *(float2*)(o + 8 * HW) = make_float2(acc[mi][nj][2], acc[mi][nj][3]);
            }
        }
    }
}

// ---------------------------------------------------------------------------
extern "C" void kernel_launch(void* const* d_in, const int* in_sizes, int n_in,
                              void* d_out, int out_size) {
    const float* x     = (const float*)d_in[0];
    const float* convs = (const float*)d_in[1];
    const float* w1    = (const float*)d_in[2];
    const float* b1    = (const float*)d_in[3];
    const float* w2    = (const float*)d_in[4];
    const float* b2    = (const float*)d_in[5];
    float* out = (float*)d_out;

    cudaFuncSetAttribute(conv_mma, cudaFuncAttributeMaxDynamicSharedMemorySize, SM_TOTAL);

    gap_kernel<<<B_ * CIN, 256>>>(x);
    routing_kernel<<<1, 32>>>(w1, b1, w2, b2);
    shift_kernel<<<B_ * CIN, 256>>>(x);
    mix_kernel<<<dim3(COUT, B_), 128>>>(convs);
    conv_mma<<<dim3((HW + 127) / 128, COUT / 128, B_), 256, SM_TOTAL>>>(out);
}

// round 15
// speedup vs baseline: 1.6316x; 1.0758x over previous
#include <cuda_runtime.h>
#include <cuda_fp16.h>
#include <cstdint>

// Problem constants
#define B_    32
#define CIN   128
#define H_    56
#define HW    3136          // 56*56
#define COUT  256
#define KTOT  1152          // CIN*9
#define R_    16
#define KERN_PER_B (COUT*KTOT)      // 294912

// Scratch (static device arrays; no runtime allocation)
__device__ float g_gap[B_ * CIN];
__device__ float g_routing[B_ * 4];
// Mixed conv kernels, k' = r*128+ci ordering, fp16: [b][m][k']
__device__ __half g_Ah[(size_t)B_ * COUT * KTOT + 64];
// 9 shifted zero-padded fp16 copies of x: [r][b][ci][n]
#define XS_ELEMS ((size_t)9 * B_ * CIN * HW)
__device__ __half g_Xh[XS_ELEMS + 8192];

// ---------------------------------------------------------------------------
// helpers
// ---------------------------------------------------------------------------
__device__ __forceinline__ uint32_t smem_u32(const void* p) {
    uint32_t a;
    asm("{ .reg .u64 t; cvta.to.shared.u64 t, %1; cvt.u32.u64 %0, t; }"
        : "=r"(a) : "l"(p));
    return a;
}
__device__ __forceinline__ void ldmx4(uint32_t* r, uint32_t addr) {
    asm volatile("ldmatrix.sync.aligned.m8n8.x4.shared.b16 {%0,%1,%2,%3}, [%4];"
                 : "=r"(r[0]), "=r"(r[1]), "=r"(r[2]), "=r"(r[3]) : "r"(addr));
}
__device__ __forceinline__ void ldmx4t(uint32_t* r, uint32_t addr) {
    asm volatile("ldmatrix.sync.aligned.m8n8.x4.trans.shared.b16 {%0,%1,%2,%3}, [%4];"
                 : "=r"(r[0]), "=r"(r[1]), "=r"(r[2]), "=r"(r[3]) : "r"(addr));
}
__device__ __forceinline__ void mma_f16(float* d, const uint32_t* a, const uint32_t* b) {
    asm volatile(
        "mma.sync.aligned.m16n8k16.row.col.f32.f16.f16.f32 "
        "{%0,%1,%2,%3},{%4,%5,%6,%7},{%8,%9},{%0,%1,%2,%3};"
        : "+f"(d[0]), "+f"(d[1]), "+f"(d[2]), "+f"(d[3])
        : "r"(a[0]), "r"(a[1]), "r"(a[2]), "r"(a[3]), "r"(b[0]), "r"(b[1]));
}
__device__ __forceinline__ void cp16(uint32_t dst, const void* src) {
    asm volatile("cp.async.cg.shared.global [%0], [%1], 16;" :: "r"(dst), "l"(src));
}
__device__ __forceinline__ void cp_commit() {
    asm volatile("cp.async.commit_group;" ::: "memory");
}
__device__ __forceinline__ uint32_t pack_h2(__half a, __half b) {
    __half2 t = __halves2half2(a, b);
    return *reinterpret_cast<uint32_t*>(&t);
}

// ---------------------------------------------------------------------------
// 1) Shift + pad x into 9 fp16 copies AND global-average-pool (fused).
//    One block per (b, ci) plane; plane staged once in smem.
// ---------------------------------------------------------------------------
__global__ void shift_kernel(const float* __restrict__ x) {
    __shared__ float plane[HW];
    __shared__ float red[8];
    const int bc = blockIdx.x;               // b*CIN + ci
    const float* src = x + (size_t)bc * HW;
    float s = 0.f;
    for (int i = threadIdx.x; i < HW; i += 256) {
        const float v = src[i];
        plane[i] = v;
        s += v;
    }
    // ---- GAP reduction (free: plane already resident) ----
    #pragma unroll
    for (int o = 16; o > 0; o >>= 1) s += __shfl_xor_sync(0xffffffffu, s, o);
    if ((threadIdx.x & 31) == 0) red[threadIdx.x >> 5] = s;
    __syncthreads();
    if (threadIdx.x < 8) {
        s = red[threadIdx.x];
        s += __shfl_xor_sync(0xffu, s, 4);
        s += __shfl_xor_sync(0xffu, s, 2);
        s += __shfl_xor_sync(0xffu, s, 1);
        if (threadIdx.x == 0) g_gap[bc] = s * (1.0f / 3136.0f);
    }
    // ---- 9 shifted fp16 copies ----
    const int b = bc >> 7, ci = bc & 127;
    for (int p = threadIdx.x; p < HW / 2; p += 256) {
        const int n0 = 2 * p;
        const int oh = n0 / H_;
        const int ow = n0 - oh * H_;         // even; ow+1 <= 55 (same row)
        #pragma unroll
        for (int r = 0; r < 9; r++) {
            const int dh = r / 3 - 1, dw = r % 3 - 1;
            const int ih = oh + dh;
            float v0 = 0.f, v1 = 0.f;
            if ((unsigned)ih < (unsigned)H_) {
                const int iw0 = ow + dw;
                if ((unsigned)iw0 < (unsigned)H_) v0 = plane[ih * H_ + iw0];
                const int iw1 = iw0 + 1;
                if ((unsigned)iw1 < (unsigned)H_) v1 = plane[ih * H_ + iw1];
            }
            const size_t off = ((size_t)(r * B_ + b) * CIN + ci) * (HW / 2) + p;
            ((uint32_t*)g_Xh)[off] = pack_h2(__float2half_rn(v0), __float2half_rn(v1));
        }
    }
}

// ---------------------------------------------------------------------------
// 2) Router MLP + softmax(logits/30)
// ---------------------------------------------------------------------------
__global__ void routing_kernel(const float* __restrict__ w1, const float* __restrict__ b1,
                               const float* __restrict__ w2, const float* __restrict__ b2) {
    const int b = threadIdx.x;
    if (b >= B_) return;
    float h[R_];
    #pragma unroll
    for (int r = 0; r < R_; r++) {
        float s = b1[r];
        for (int c = 0; c < CIN; c++) s += g_gap[b * CIN + c] * w1[r * CIN + c];
        h[r] = fmaxf(s, 0.f);
    }
    float lg[4];
    float mx = -1e30f;
    #pragma unroll
    for (int e = 0; e < 4; e++) {
        float s = b2[e];
        #pragma unroll
        for (int r = 0; r < R_; r++) s += h[r] * w2[e * R_ + r];
        lg[e] = s * (1.0f / 30.0f);
        mx = fmaxf(mx, lg[e]);
    }
    float den = 0.f;
    #pragma unroll
    for (int e = 0; e < 4; e++) { lg[e] = __expf(lg[e] - mx); den += lg[e]; }
    const float inv = 1.0f / den;
    #pragma unroll
    for (int e = 0; e < 4; e++) g_routing[b * 4 + e] = lg[e] * inv;
}

// ---------------------------------------------------------------------------
// 3) Mix expert kernels -> g_Ah[b][m][k'] with k' = r*128+ci, fp16.
//    One block per m-row: stage 4 expert rows in smem COALESCED, then
//    gather per-b from smem with fully coalesced writes.
// ---------------------------------------------------------------------------
__global__ void mix_kernel(const float* __restrict__ convs) {
    __shared__ float sc[4][KTOT];
    const int m = blockIdx.x;
    for (int e = 0; e < 4; e++)
        for (int i = threadIdx.x; i < KTOT; i += 256)
            sc[e][i] = convs[(size_t)e * KERN_PER_B + m * KTOT + i];
    __syncthreads();
    for (int b = 0; b < B_; b++) {
        const float r0 = g_routing[b * 4 + 0];
        const float r1 = g_routing[b * 4 + 1];
        const float r2 = g_routing[b * 4 + 2];
        const float r3 = g_routing[b * 4 + 3];
        for (int p = threadIdx.x; p < KTOT / 2; p += 256) {
            const int r = p >> 6;
            const int i0 = (p & 63) * 18 + r;     // ci*9 + r with ci = (p&63)*2
            const float v0 = r0 * sc[0][i0] + r1 * sc[1][i0] + r2 * sc[2][i0] + r3 * sc[3][i0];
            const int i1 = i0 + 9;
            const float v1 = r0 * sc[0][i1] + r1 * sc[1][i1] + r2 * sc[2][i1] + r3 * sc[3][i1];
            const size_t off = (size_t)(b * COUT + m) * (KTOT / 2) + p;
            ((uint32_t*)g_Ah)[off] = pack_h2(__float2half_rn(v0), __float2half_rn(v1));
        }
    }
}

// ---------------------------------------------------------------------------
// 4) Per-sample GEMM on mma.sync (single-pass fp16), BK=64 (18 stages),
//    3-stage cp.async ring, ONE __syncthreads per stage
//    (wait -> sync -> prefetch -> compute). UNCHANGED from R14.
// ---------------------------------------------------------------------------
#define STG    32768
#define NSTG   3
#define SM_A(buf)  ((buf) * STG)
#define SM_B(buf)  ((buf) * STG + 16384)
#define SM_TOTAL   (NSTG * STG)

__global__ void __launch_bounds__(256, 2)
conv_mma(float* __restrict__ out) {
    extern __shared__ __align__(128) char smem[];
    const uint32_t sb = smem_u32(smem);

    const int tid  = threadIdx.x;
    const int wid  = tid >> 5;
    const int lane = tid & 31;
    const int wm   = wid & 1;          // 2 warps along m
    const int wn   = wid >> 1;         // 4 warps along n

    const int b  = blockIdx.z;
    const int m0 = blockIdx.y * 128;
    const int n0 = blockIdx.x * 128;

    float acc[4][4][4];
    #pragma unroll
    for (int i = 0; i < 4; i++)
        #pragma unroll
        for (int j = 0; j < 4; j++)
            #pragma unroll
            for (int q = 0; q < 4; q++) acc[i][j][q] = 0.f;

    // ---- stage loader (A: 1024 cp16, B: 1024 cp16 across 256 threads) ----
    auto load_stage = [&](int s, int buf) {
        const int r   = s >> 1;
        const int ci0 = (s & 1) * 64;
        // A: row m 0..127, chunk c 0..7 (128B rows)
        #pragma unroll
        for (int q = 0; q < 4; q++) {
            const int id  = q * 256 + tid;
            const int row = id >> 3;
            const int c   = id & 7;
            const __half* src =
                g_Ah + (size_t)(b * COUT + m0 + row) * KTOT + s * 64 + c * 8;
            cp16(sb + SM_A(buf) + row * 128 + ((c ^ (row & 7)) * 16), src);
        }
        // B: krow 0..63, chunk c 0..15 (256B rows)
        #pragma unroll
        for (int q = 0; q < 4; q++) {
            const int id = q * 256 + tid;
            const int kr = id >> 4;
            const int c  = id & 15;
            const __half* src =
                g_Xh + (size_t)((r * B_ + b) * CIN + ci0 + kr) * HW + n0 + c * 8;
            cp16(sb + SM_B(buf) + kr * 256 + ((c ^ (kr & 7)) * 16), src);
        }
        cp_commit();
    };

    load_stage(0, 0);
    load_stage(1, 1);

    for (int s = 0; s < 18; s++) {
        const int buf = s % 3;
        if (s < 17) asm volatile("cp.async.wait_group 1;" ::: "memory");
        else        asm volatile("cp.async.wait_group 0;" ::: "memory");
        __syncthreads();
        if (s + 2 < 18) load_stage(s + 2, (s + 2) % 3);

        #pragma unroll
        for (int ks = 0; ks < 4; ks++) {
            uint32_t ah[4][4];
            #pragma unroll
            for (int mi = 0; mi < 4; mi++) {
                const int row = wm * 64 + mi * 16 + (lane & 15);
                const int cl  = ks * 2 + (lane >> 4);
                ldmx4(ah[mi], sb + SM_A(buf) + row * 128 + ((cl ^ (row & 7)) * 16));
            }
            uint32_t bh[4][2];
            #pragma unroll
            for (int ni = 0; ni < 2; ni++) {
                const int mat = lane >> 3, j = lane & 7;
                const int kr  = ks * 16 + (mat & 1) * 8 + j;
                const int nc  = wn * 4 + ni * 2 + (mat >> 1);
                uint32_t t[4];
                ldmx4t(t, sb + SM_B(buf) + kr * 256 + ((nc ^ (kr & 7)) * 16));
                bh[ni * 2 + 0][0] = t[0]; bh[ni * 2 + 0][1] = t[1];
                bh[ni * 2 + 1][0] = t[2]; bh[ni * 2 + 1][1] = t[3];
            }
            #pragma unroll
            for (int mi = 0; mi < 4; mi++)
                #pragma unroll
                for (int nj = 0; nj < 4; nj++)
                    mma_f16(acc[mi][nj], ah[mi], bh[nj]);
        }
    }

    // ---- epilogue ----
    #pragma unroll
    for (int mi = 0; mi < 4; mi++) {
        const int m = m0 + wm * 64 + mi * 16 + (lane >> 2);
        #pragma unroll
        for (int nj = 0; nj < 4; nj++) {
            const int nn = n0 + wn * 32 + nj * 8 + (lane & 3) * 2;
            if (nn < HW) {
                float* o = out + (size_t)(b * COUT + m) * HW + nn;
                *(float2*)o = make_float2(acc[mi][nj][0], acc[mi][nj][1]);
                *(float2*)(o + 8 * HW) = make_float2(acc[mi][nj][2], acc[mi][nj][3]);
            }
        }
    }
}

// ---------------------------------------------------------------------------
extern "C" void kernel_launch(void* const* d_in, const int* in_sizes, int n_in,
                              void* d_out, int out_size) {
    const float* x     = (const float*)d_in[0];
    const float* convs = (const float*)d_in[1];
    const float* w1    = (const float*)d_in[2];
    const float* b1    = (const float*)d_in[3];
    const float* w2    = (const float*)d_in[4];
    const float* b2    = (const float*)d_in[5];
    float* out = (float*)d_out;

    cudaFuncSetAttribute(conv_mma, cudaFuncAttributeMaxDynamicSharedMemorySize, SM_TOTAL);

    shift_kernel<<<B_ * CIN, 256>>>(x);             // also produces g_gap
    routing_kernel<<<1, 32>>>(w1, b1, w2, b2);
    mix_kernel<<<COUT, 256>>>(convs);
    conv_mma<<<dim3((HW + 127) / 128, COUT / 128, B_), 256, SM_TOTAL>>>(out);
}

// round 16
// speedup vs baseline: 1.6966x; 1.0398x over previous
#include <cuda_runtime.h>
#include <cuda_fp16.h>
#include <cstdint>

// Problem constants
#define B_    32
#define CIN   128
#define H_    56
#define HW    3136          // 56*56
#define COUT  256
#define KTOT  1152          // CIN*9
#define R_    16
#define KERN_PER_B (COUT*KTOT)      // 294912
#define PLANE 3248          // 58 rows * 56 (1 zero pad row above/below)

// Scratch (static device arrays; no runtime allocation)
__device__ float g_gap[B_ * CIN];
__device__ float g_routing[B_ * 4];
// Mixed conv kernels, k' = r*128+ci ordering, fp16: [b][m][k']
__device__ __half g_Ah[(size_t)B_ * COUT * KTOT + 64];
// 3 dw-shifted, vertically padded fp16 copies of x: [dw][b][ci][58*56]
// pad rows (ih=-1, ih=56) are NEVER written -> stay zero (static zero-init)
__device__ __half g_X3[(size_t)3 * B_ * CIN * PLANE + 8192];

// ---------------------------------------------------------------------------
// helpers
// ---------------------------------------------------------------------------
__device__ __forceinline__ uint32_t smem_u32(const void* p) {
    uint32_t a;
    asm("{ .reg .u64 t; cvta.to.shared.u64 t, %1; cvt.u32.u64 %0, t; }"
        : "=r"(a) : "l"(p));
    return a;
}
__device__ __forceinline__ void ldmx4(uint32_t* r, uint32_t addr) {
    asm volatile("ldmatrix.sync.aligned.m8n8.x4.shared.b16 {%0,%1,%2,%3}, [%4];"
                 : "=r"(r[0]), "=r"(r[1]), "=r"(r[2]), "=r"(r[3]) : "r"(addr));
}
__device__ __forceinline__ void ldmx4t(uint32_t* r, uint32_t addr) {
    asm volatile("ldmatrix.sync.aligned.m8n8.x4.trans.shared.b16 {%0,%1,%2,%3}, [%4];"
                 : "=r"(r[0]), "=r"(r[1]), "=r"(r[2]), "=r"(r[3]) : "r"(addr));
}
__device__ __forceinline__ void mma_f16(float* d, const uint32_t* a, const uint32_t* b) {
    asm volatile(
        "mma.sync.aligned.m16n8k16.row.col.f32.f16.f16.f32 "
        "{%0,%1,%2,%3},{%4,%5,%6,%7},{%8,%9},{%0,%1,%2,%3};"
        : "+f"(d[0]), "+f"(d[1]), "+f"(d[2]), "+f"(d[3])
        : "r"(a[0]), "r"(a[1]), "r"(a[2]), "r"(a[3]), "r"(b[0]), "r"(b[1]));
}
__device__ __forceinline__ void cp16(uint32_t dst, const void* src) {
    asm volatile("cp.async.cg.shared.global [%0], [%1], 16;" :: "r"(dst), "l"(src));
}
__device__ __forceinline__ void cp_commit() {
    asm volatile("cp.async.commit_group;" ::: "memory");
}
__device__ __forceinline__ uint32_t pack_h2(__half a, __half b) {
    __half2 t = __halves2half2(a, b);
    return *reinterpret_cast<uint32_t*>(&t);
}

// ---------------------------------------------------------------------------
// 1) Shift(dw only) + pad + fp16 convert x into 3 copies AND GAP (fused).
//    One block per (b, ci) plane.
// ---------------------------------------------------------------------------
__global__ void shift_kernel(const float* __restrict__ x) {
    __shared__ float plane[HW];
    __shared__ float red[8];
    const int bc = blockIdx.x;               // b*CIN + ci
    const float* src = x + (size_t)bc * HW;
    float s = 0.f;
    for (int i = threadIdx.x; i < HW; i += 256) {
        const float v = src[i];
        plane[i] = v;
        s += v;
    }
    // ---- GAP reduction ----
    #pragma unroll
    for (int o = 16; o > 0; o >>= 1) s += __shfl_xor_sync(0xffffffffu, s, o);
    if ((threadIdx.x & 31) == 0) red[threadIdx.x >> 5] = s;
    __syncthreads();
    if (threadIdx.x < 8) {
        s = red[threadIdx.x];
        s += __shfl_xor_sync(0xffu, s, 4);
        s += __shfl_xor_sync(0xffu, s, 2);
        s += __shfl_xor_sync(0xffu, s, 1);
        if (threadIdx.x == 0) g_gap[bc] = s * (1.0f / 3136.0f);
    }
    // ---- 3 dw-shifted fp16 copies (rows written at padded offset +56) ----
    const int b = bc >> 7, ci = bc & 127;
    for (int p = threadIdx.x; p < HW / 2; p += 256) {
        const int n0 = 2 * p;
        const int oh = n0 / H_;
        const int ow = n0 - oh * H_;         // even; ow+1 <= 55 (same row)
        #pragma unroll
        for (int dwi = 0; dwi < 3; dwi++) {
            const int dw = dwi - 1;
            const int iw0 = ow + dw;
            const int iw1 = iw0 + 1;
            float v0 = ((unsigned)iw0 < (unsigned)H_) ? plane[oh * H_ + iw0] : 0.f;
            float v1 = ((unsigned)iw1 < (unsigned)H_) ? plane[oh * H_ + iw1] : 0.f;
            const size_t off = ((size_t)(dwi * B_ + b) * CIN + ci) * (PLANE / 2) + 28 + p;
            ((uint32_t*)g_X3)[off] = pack_h2(__float2half_rn(v0), __float2half_rn(v1));
        }
    }
}

// ---------------------------------------------------------------------------
// 2) Router MLP + softmax(logits/30)
// ---------------------------------------------------------------------------
__global__ void routing_kernel(const float* __restrict__ w1, const float* __restrict__ b1,
                               const float* __restrict__ w2, const float* __restrict__ b2) {
    const int b = threadIdx.x;
    if (b >= B_) return;
    float h[R_];
    #pragma unroll
    for (int r = 0; r < R_; r++) {
        float s = b1[r];
        for (int c = 0; c < CIN; c++) s += g_gap[b * CIN + c] * w1[r * CIN + c];
        h[r] = fmaxf(s, 0.f);
    }
    float lg[4];
    float mx = -1e30f;
    #pragma unroll
    for (int e = 0; e < 4; e++) {
        float s = b2[e];
        #pragma unroll
        for (int r = 0; r < R_; r++) s += h[r] * w2[e * R_ + r];
        lg[e] = s * (1.0f / 30.0f);
        mx = fmaxf(mx, lg[e]);
    }
    float den = 0.f;
    #pragma unroll
    for (int e = 0; e < 4; e++) { lg[e] = __expf(lg[e] - mx); den += lg[e]; }
    const float inv = 1.0f / den;
    #pragma unroll
    for (int e = 0; e < 4; e++) g_routing[b * 4 + e] = lg[e] * inv;
}

// ---------------------------------------------------------------------------
// 3) Mix expert kernels -> g_Ah[b][m][k'] with k' = r*128+ci, fp16.
//    One block per m-row: stage 4 expert rows in smem coalesced.
// ---------------------------------------------------------------------------
__global__ void mix_kernel(const float* __restrict__ convs) {
    __shared__ float sc[4][KTOT];
    const int m = blockIdx.x;
    for (int e = 0; e < 4; e++)
        for (int i = threadIdx.x; i < KTOT; i += 256)
            sc[e][i] = convs[(size_t)e * KERN_PER_B + m * KTOT + i];
    __syncthreads();
    for (int b = 0; b < B_; b++) {
        const float r0 = g_routing[b * 4 + 0];
        const float r1 = g_routing[b * 4 + 1];
        const float r2 = g_routing[b * 4 + 2];
        const float r3 = g_routing[b * 4 + 3];
        for (int p = threadIdx.x; p < KTOT / 2; p += 256) {
            const int r = p >> 6;
            const int i0 = (p & 63) * 18 + r;     // ci*9 + r with ci = (p&63)*2
            const float v0 = r0 * sc[0][i0] + r1 * sc[1][i0] + r2 * sc[2][i0] + r3 * sc[3][i0];
            const int i1 = i0 + 9;
            const float v1 = r0 * sc[0][i1] + r1 * sc[1][i1] + r2 * sc[2][i1] + r3 * sc[3][i1];
            const size_t off = (size_t)(b * COUT + m) * (KTOT / 2) + p;
            ((uint32_t*)g_Ah)[off] = pack_h2(__float2half_rn(v0), __float2half_rn(v1));
        }
    }
}

// ---------------------------------------------------------------------------
// 4) Per-sample GEMM on mma.sync (single-pass fp16), BK=64 (18 stages),
//    3-stage cp.async ring (wait -> sync -> prefetch -> compute).
//    B loader reads the dw-copy with a +/-56-elem row offset for dh
//    (112 B, 16 B-aligned; pad rows supply vertical zeros).
// ---------------------------------------------------------------------------
#define STG    32768
#define NSTG   3
#define SM_A(buf)  ((buf) * STG)
#define SM_B(buf)  ((buf) * STG + 16384)
#define SM_TOTAL   (NSTG * STG)

__global__ void __launch_bounds__(256, 2)
conv_mma(float* __restrict__ out) {
    extern __shared__ __align__(128) char smem[];
    const uint32_t sb = smem_u32(smem);

    const int tid  = threadIdx.x;
    const int wid  = tid >> 5;
    const int lane = tid & 31;
    const int wm   = wid & 1;          // 2 warps along m
    const int wn   = wid >> 1;         // 4 warps along n

    const int b  = blockIdx.z;
    const int m0 = blockIdx.y * 128;
    const int n0 = blockIdx.x * 128;

    float acc[4][4][4];
    #pragma unroll
    for (int i = 0; i < 4; i++)
        #pragma unroll
        for (int j = 0; j < 4; j++)
            #pragma unroll
            for (int q = 0; q < 4; q++) acc[i][j][q] = 0.f;

    // ---- stage loader (A: 1024 cp16, B: 1024 cp16 across 256 threads) ----
    auto load_stage = [&](int s, int buf) {
        const int r   = s >> 1;              // 0..8 (constant per stage)
        const int ci0 = (s & 1) * 64;
        const int dwi = r - (r / 3) * 3;     // r % 3
        const int dh  = r / 3 - 1;
        // A: row m 0..127, chunk c 0..7 (128B rows)
        #pragma unroll
        for (int q = 0; q < 4; q++) {
            const int id  = q * 256 + tid;
            const int row = id >> 3;
            const int c   = id & 7;
            const __half* src =
                g_Ah + (size_t)(b * COUT + m0 + row) * KTOT + s * 64 + c * 8;
            cp16(sb + SM_A(buf) + row * 128 + ((c ^ (row & 7)) * 16), src);
        }
        // B: krow 0..63 (ci = ci0+kr), chunk c 0..15 (256B rows)
        #pragma unroll
        for (int q = 0; q < 4; q++) {
            const int id = q * 256 + tid;
            const int kr = id >> 4;
            const int c  = id & 15;
            const __half* src =
                g_X3 + ((size_t)(dwi * B_ + b) * CIN + ci0 + kr) * PLANE
                     + (dh + 1) * 56 + n0 + c * 8;
            cp16(sb + SM_B(buf) + kr * 256 + ((c ^ (kr & 7)) * 16), src);
        }
        cp_commit();
    };

    load_stage(0, 0);
    load_stage(1, 1);

    for (int s = 0; s < 18; s++) {
        const int buf = s % 3;
        if (s < 17) asm volatile("cp.async.wait_group 1;" ::: "memory");
        else        asm volatile("cp.async.wait_group 0;" ::: "memory");
        __syncthreads();
        if (s + 2 < 18) load_stage(s + 2, (s + 2) % 3);

        #pragma unroll
        for (int ks = 0; ks < 4; ks++) {
            uint32_t ah[4][4];
            #pragma unroll
            for (int mi = 0; mi < 4; mi++) {
                const int row = wm * 64 + mi * 16 + (lane & 15);
                const int cl  = ks * 2 + (lane >> 4);
                ldmx4(ah[mi], sb + SM_A(buf) + row * 128 + ((cl ^ (row & 7)) * 16));
            }
            uint32_t bh[4][2];
            #pragma unroll
            for (int ni = 0; ni < 2; ni++) {
                const int mat = lane >> 3, j = lane & 7;
                const int kr  = ks * 16 + (mat & 1) * 8 + j;
                const int nc  = wn * 4 + ni * 2 + (mat >> 1);
                uint32_t t[4];
                ldmx4t(t, sb + SM_B(buf) + kr * 256 + ((nc ^ (kr & 7)) * 16));
                bh[ni * 2 + 0][0] = t[0]; bh[ni * 2 + 0][1] = t[1];
                bh[ni * 2 + 1][0] = t[2]; bh[ni * 2 + 1][1] = t[3];
            }
            #pragma unroll
            for (int mi = 0; mi < 4; mi++)
                #pragma unroll
                for (int nj = 0; nj < 4; nj++)
                    mma_f16(acc[mi][nj], ah[mi], bh[nj]);
        }
    }

    // ---- epilogue ----
    #pragma unroll
    for (int mi = 0; mi < 4; mi++) {
        const int m = m0 + wm * 64 + mi * 16 + (lane >> 2);
        #pragma unroll
        for (int nj = 0; nj < 4; nj++) {
            const int nn = n0 + wn * 32 + nj * 8 + (lane & 3) * 2;
            if (nn < HW) {
                float* o = out + (size_t)(b * COUT + m) * HW + nn;
                *(float2*)o = make_float2(acc[mi][nj][0], acc[mi][nj][1]);
                *(float2*)(o + 8 * HW) = make_float2(acc[mi][nj][2], acc[mi][nj][3]);
            }
        }
    }
}

// ---------------------------------------------------------------------------
extern "C" void kernel_launch(void* const* d_in, const int* in_sizes, int n_in,
                              void* d_out, int out_size) {
    const float* x     = (const float*)d_in[0];
    const float* convs = (const float*)d_in[1];
    const float* w1    = (const float*)d_in[2];
    const float* b1    = (const float*)d_in[3];
    const float* w2    = (const float*)d_in[4];
    const float* b2    = (const float*)d_in[5];
    float* out = (float*)d_out;

    cudaFuncSetAttribute(conv_mma, cudaFuncAttributeMaxDynamicSharedMemorySize, SM_TOTAL);

    shift_kernel<<<B_ * CIN, 256>>>(x);             // also produces g_gap
    routing_kernel<<<1, 32>>>(w1, b1, w2, b2);
    mix_kernel<<<COUT, 256>>>(convs);
    conv_mma<<<dim3((HW + 127) / 128, COUT / 128, B_), 256, SM_TOTAL>>>(out);
}